// round 7
// baseline (speedup 1.0000x reference)
#include <cuda_runtime.h>
#include <cstdint>

// Problem constants (fixed by the reference)
#define NN 50000
#define D  128
#define EMAX 1600000

// Scratch globals (~3.6 MB total). Row ids fit uint16 since NN < 65536.
__device__ int            g_off[NN + 1];
__device__ int            g_cur[NN];
__device__ unsigned short g_csr[EMAX];
__device__ int            g_is64;

// ---------------------------------------------------------------------------
// Detect whether edge_index is int64 or int32.
// ---------------------------------------------------------------------------
__global__ void detect_kernel(const void* __restrict__ idx) {
    if (blockIdx.x == 0 && threadIdx.x == 0) {
        const long long* p = (const long long*)idx;
        int ok = 1;
        #pragma unroll
        for (int i = 0; i < 8; i++) {
            long long v = p[i];
            if (v < 0 || v >= NN) ok = 0;
        }
        g_is64 = ok;
    }
}

// ---------------------------------------------------------------------------
// Zero per-node cursors (used as counts first)
// ---------------------------------------------------------------------------
__global__ void zero_cnt_kernel() {
    int i = blockIdx.x * blockDim.x + threadIdx.x;
    if (i < NN) g_cur[i] = 0;
}

// ---------------------------------------------------------------------------
// Histogram of destination (col) indices
// ---------------------------------------------------------------------------
__global__ void count_kernel(const void* __restrict__ idx, int E) {
    int e = blockIdx.x * blockDim.x + threadIdx.x;
    if (e >= E) return;
    int c;
    if (g_is64) c = (int)__ldg((const long long*)idx + E + e);
    else        c = __ldg((const int*)idx + E + e);
    atomicAdd(g_cur + c, 1);
}

// ---------------------------------------------------------------------------
// Exclusive scan of counts -> g_off; g_cur reset to start offsets (cursors).
// Single block, 1024 threads, each handles ceil(NN/1024)=49 nodes.
// ---------------------------------------------------------------------------
__global__ __launch_bounds__(1024)
void scan_kernel(int n) {
    const int C = (NN + 1023) / 1024;  // 49
    int t = threadIdx.x;
    int beg = t * C;
    int end = beg + C; if (end > n) end = n;
    if (beg > n) beg = n;

    int s = 0;
    for (int i = beg; i < end; i++) s += g_cur[i];

    // exclusive prefix of s across 1024 threads
    __shared__ int wsum[32];
    int lane = t & 31, w = t >> 5;
    int v = s;
    #pragma unroll
    for (int d = 1; d < 32; d <<= 1) {
        int u = __shfl_up_sync(0xffffffffu, v, d);
        if (lane >= d) v += u;
    }
    if (lane == 31) wsum[w] = v;
    __syncthreads();
    if (w == 0) {
        int ws = wsum[lane];
        #pragma unroll
        for (int d = 1; d < 32; d <<= 1) {
            int u = __shfl_up_sync(0xffffffffu, ws, d);
            if (lane >= d) ws += u;
        }
        wsum[lane] = ws;
    }
    __syncthreads();
    int offset = v - s + (w > 0 ? wsum[w - 1] : 0);   // exclusive prefix

    int run = offset;
    for (int i = beg; i < end; i++) {
        int c = g_cur[i];
        g_off[i] = run;
        g_cur[i] = run;
        run += c;
    }
    if (t == 1023) g_off[n] = run;
}

// ---------------------------------------------------------------------------
// Fill CSR: group source row ids by destination
// ---------------------------------------------------------------------------
__global__ void fill_kernel(const void* __restrict__ idx, int E) {
    int e = blockIdx.x * blockDim.x + threadIdx.x;
    if (e >= E) return;
    int r, c;
    if (g_is64) {
        const long long* p = (const long long*)idx;
        r = (int)__ldg(p + e);
        c = (int)__ldg(p + E + e);
    } else {
        const int* p = (const int*)idx;
        r = __ldg(p + e);
        c = __ldg(p + E + e);
    }
    int pos = atomicAdd(g_cur + c, 1);
    g_csr[pos] = (unsigned short)r;
}

// ---------------------------------------------------------------------------
// Fused gather-aggregate + tf32 tensor-core GEMM.  BM = 64 rows per block so
// everything fits in STATIC shared memory (44 KB) — no dynamic smem, no
// cudaFuncSetAttribute, no static host guards.
//   A[n] = deg>0 ? (sum_{r in nbr(n)} x[r]) / deg : x[n]
//   out[n][j] = sum_k A[n][k] * W[j][k] + b[j]
// Phase 1 (gather): 8 warps x 8 rows; lanes cover 128 features (1 float4
//   each); neighbor ids chunk-loaded coalesced + shfl-broadcast; result
//   scaled, tf32-converted into As[m][k].
// Phase 2 (mma): 8 warps in 2x4 grid; each warp a 32x32 patch = 2x4
//   m16n8k8 tf32 tiles; W staged in 16-wide K slabs Ws[n][k].
// ---------------------------------------------------------------------------
#define BM  64
#define SPA 132   // As row pitch (u32): 128 + 4 pad
#define SPW 20    // Ws row pitch (u32): 16 + 4 pad

__device__ __forceinline__ uint32_t f2tf32(float v) {
    uint32_t u;
    asm("cvt.rna.tf32.f32 %0, %1;" : "=r"(u) : "f"(v));
    return u;
}

__global__ __launch_bounds__(256)
void fused_kernel(const float4* __restrict__ x4,
                  const float* __restrict__ W,
                  const float* __restrict__ bias,
                  float* __restrict__ out, int N) {
    __shared__ uint32_t As[BM * SPA];    // 33792 B
    __shared__ uint32_t Ws[128 * SPW];   // 10240 B

    int tid  = threadIdx.x;
    int row0 = blockIdx.x * BM;
    int wid  = tid >> 5;
    int lane = tid & 31;

    // ---------------- Phase 1: gather-aggregate into As ----------------
    for (int rr = wid; rr < BM; rr += 8) {
        int n = row0 + rr;
        float4 acc = make_float4(0.f, 0.f, 0.f, 0.f);
        float scale = 1.0f;
        if (n < N) {
            int beg = g_off[n], end = g_off[n + 1];
            int deg = end - beg;
            if (deg == 0) {
                acc = __ldg(x4 + (size_t)n * 32 + lane);
            } else {
                for (int b = beg; b < end; b += 32) {
                    int rid = 0;
                    if (b + lane < end) rid = g_csr[b + lane];
                    int m = end - b; if (m > 32) m = 32;
                    #pragma unroll 4
                    for (int j = 0; j < m; j++) {
                        int r = __shfl_sync(0xffffffffu, rid, j);
                        float4 v = __ldg(x4 + (size_t)r * 32 + lane);
                        acc.x += v.x; acc.y += v.y; acc.z += v.z; acc.w += v.w;
                    }
                }
                scale = 1.0f / (float)deg;
            }
        }
        uint4 o;
        o.x = f2tf32(acc.x * scale);
        o.y = f2tf32(acc.y * scale);
        o.z = f2tf32(acc.z * scale);
        o.w = f2tf32(acc.w * scale);
        *(uint4*)(As + (size_t)rr * SPA + lane * 4) = o;
    }
    __syncthreads();

    // ---------------- Phase 2: tensor-core MMA ----------------
    int g  = lane >> 2;     // 0..7
    int c4 = lane & 3;      // 0..3
    int wy = wid >> 2;      // 0..1 -> 32 rows each
    int wx = wid & 3;       // 0..3 -> 32 cols each

    float acc[2][4][4];
    #pragma unroll
    for (int i = 0; i < 2; i++)
        #pragma unroll
        for (int j = 0; j < 4; j++)
            #pragma unroll
            for (int q = 0; q < 4; q++) acc[i][j][q] = 0.f;

    for (int k0 = 0; k0 < 128; k0 += 16) {
        // load W slab: Ws[n][kk] = tf32(W[n][k0+kk]); 512 float4 / 256 thr
        #pragma unroll
        for (int q = 0; q < 2; q++) {
            int lin  = tid + q * 256;      // 0..511
            int nrow = lin >> 2;           // 0..127
            int f4   = lin & 3;            // 0..3 -> 16 floats
            float4 wv = *(const float4*)(W + (size_t)nrow * 128 + k0 + f4 * 4);
            uint4 o;
            o.x = f2tf32(wv.x); o.y = f2tf32(wv.y);
            o.z = f2tf32(wv.z); o.w = f2tf32(wv.w);
            *(uint4*)(Ws + (size_t)nrow * SPW + f4 * 4) = o;
        }
        __syncthreads();

        #pragma unroll
        for (int ks = 0; ks < 16; ks += 8) {
            uint32_t bf[4][2];
            #pragma unroll
            for (int j = 0; j < 4; j++) {
                int n0 = wx * 32 + j * 8;
                bf[j][0] = Ws[(size_t)(n0 + g) * SPW + ks + c4];
                bf[j][1] = Ws[(size_t)(n0 + g) * SPW + ks + c4 + 4];
            }
            #pragma unroll
            for (int i = 0; i < 2; i++) {
                int m0 = wy * 32 + i * 16;
                int kk = k0 + ks;
                uint32_t a0 = As[(size_t)(m0 + g) * SPA + kk + c4];
                uint32_t a1 = As[(size_t)(m0 + g + 8) * SPA + kk + c4];
                uint32_t a2 = As[(size_t)(m0 + g) * SPA + kk + c4 + 4];
                uint32_t a3 = As[(size_t)(m0 + g + 8) * SPA + kk + c4 + 4];
                #pragma unroll
                for (int j = 0; j < 4; j++) {
                    asm volatile(
                        "mma.sync.aligned.m16n8k8.row.col.f32.tf32.tf32.f32 "
                        "{%0,%1,%2,%3}, {%4,%5,%6,%7}, {%8,%9}, {%0,%1,%2,%3};"
                        : "+f"(acc[i][j][0]), "+f"(acc[i][j][1]),
                          "+f"(acc[i][j][2]), "+f"(acc[i][j][3])
                        : "r"(a0), "r"(a1), "r"(a2), "r"(a3),
                          "r"(bf[j][0]), "r"(bf[j][1]));
                }
            }
        }
        __syncthreads();
    }

    // ---------------- epilogue: bias + store ----------------
    #pragma unroll
    for (int j = 0; j < 4; j++) {
        int n = wx * 32 + j * 8 + 2 * c4;
        float2 bb = *(const float2*)(bias + n);
        #pragma unroll
        for (int i = 0; i < 2; i++) {
            int mr = row0 + wy * 32 + i * 16 + g;
            if (mr < N) {
                float2 o;
                o.x = acc[i][j][0] + bb.x;
                o.y = acc[i][j][1] + bb.y;
                *(float2*)(out + (size_t)mr * 128 + n) = o;
            }
            int mr2 = mr + 8;
            if (mr2 < N) {
                float2 o;
                o.x = acc[i][j][2] + bb.x;
                o.y = acc[i][j][3] + bb.y;
                *(float2*)(out + (size_t)mr2 * 128 + n) = o;
            }
        }
    }
}

// ---------------------------------------------------------------------------
extern "C" void kernel_launch(void* const* d_in, const int* in_sizes, int n_in,
                              void* d_out, int out_size) {
    const float* x    = (const float*)d_in[0];
    const void*  idx  = d_in[1];
    const float* W    = (const float*)d_in[2];
    const float* bias = (const float*)d_in[3];
    float* out = (float*)d_out;

    int E = in_sizes[1] / 2;      // 1,600,000 regardless of int32/int64
    int N = in_sizes[0] / D;      // 50,000

    detect_kernel<<<1, 32>>>(idx);
    zero_cnt_kernel<<<(NN + 255) / 256, 256>>>();
    count_kernel<<<(E + 255) / 256, 256>>>(idx, E);
    scan_kernel<<<1, 1024>>>(NN);
    fill_kernel<<<(E + 255) / 256, 256>>>(idx, E);
    fused_kernel<<<(N + BM - 1) / BM, 256>>>((const float4*)x, W, bias, out, N);
}

// round 8
// speedup vs baseline: 1.4466x; 1.4466x over previous
#include <cuda_runtime.h>
#include <cstdint>

// Problem constants (fixed by the reference)
#define NN 50000
#define D  128
#define EMAX 1600000
#define SBLK 256
#define NBLK ((NN + SBLK - 1) / SBLK)   // 196

// Scratch globals (~3.6 MB total). Row ids fit uint16 since NN < 65536.
__device__ int            g_off[NN + 1];
__device__ int            g_cur[NN];
__device__ int            g_bsum[NBLK];
__device__ unsigned short g_csr[EMAX];
__device__ int            g_is64;

// ---------------------------------------------------------------------------
// Detect whether edge_index is int64 or int32.
// ---------------------------------------------------------------------------
__global__ void detect_kernel(const void* __restrict__ idx) {
    if (blockIdx.x == 0 && threadIdx.x == 0) {
        const long long* p = (const long long*)idx;
        int ok = 1;
        #pragma unroll
        for (int i = 0; i < 8; i++) {
            long long v = p[i];
            if (v < 0 || v >= NN) ok = 0;
        }
        g_is64 = ok;
    }
}

// ---------------------------------------------------------------------------
// Zero per-node cursors (used as counts first)
// ---------------------------------------------------------------------------
__global__ void zero_cnt_kernel() {
    int i = blockIdx.x * blockDim.x + threadIdx.x;
    if (i < NN) g_cur[i] = 0;
}

// ---------------------------------------------------------------------------
// Histogram of destination (col) indices
// ---------------------------------------------------------------------------
__global__ void count_kernel(const void* __restrict__ idx, int E) {
    int e = blockIdx.x * blockDim.x + threadIdx.x;
    if (e >= E) return;
    int c;
    if (g_is64) c = (int)__ldg((const long long*)idx + E + e);
    else        c = __ldg((const int*)idx + E + e);
    atomicAdd(g_cur + c, 1);
}

// ---------------------------------------------------------------------------
// Grid-wide exclusive scan of g_cur -> g_off (3 phases, all parallel).
// Block-local scan helper: 256-element exclusive scan via warp shfl + smem.
// ---------------------------------------------------------------------------
__device__ __forceinline__ int block_excl_scan_256(int v, int* total) {
    __shared__ int wsum[8];
    int lane = threadIdx.x & 31, w = threadIdx.x >> 5;
    int inc = v;
    #pragma unroll
    for (int d = 1; d < 32; d <<= 1) {
        int u = __shfl_up_sync(0xffffffffu, inc, d);
        if (lane >= d) inc += u;
    }
    if (lane == 31) wsum[w] = inc;
    __syncthreads();
    if (w == 0 && lane < 8) {
        int ws = wsum[lane];
        #pragma unroll
        for (int d = 1; d < 8; d <<= 1) {
            int u = __shfl_up_sync(0x000000ffu, ws, d);
            if (lane >= d) ws += u;
        }
        wsum[lane] = ws;
    }
    __syncthreads();
    int base = (w > 0) ? wsum[w - 1] : 0;
    if (total) *total = wsum[7];
    return base + inc - v;   // exclusive prefix
}

// Phase 1: per-block sums of counts
__global__ __launch_bounds__(SBLK)
void scan_p1_kernel() {
    int n = blockIdx.x * SBLK + threadIdx.x;
    int c = (n < NN) ? g_cur[n] : 0;
    int tot;
    block_excl_scan_256(c, &tot);
    if (threadIdx.x == 0) g_bsum[blockIdx.x] = tot;
}

// Phase 2: exclusive scan of the 196 block sums (single block)
__global__ __launch_bounds__(SBLK)
void scan_p2_kernel() {
    int t = threadIdx.x;
    int c = (t < NBLK) ? g_bsum[t] : 0;
    int ex = block_excl_scan_256(c, nullptr);
    if (t < NBLK) g_bsum[t] = ex;
}

// Phase 3: local exclusive scan + block offset -> g_off, g_cur (cursors)
__global__ __launch_bounds__(SBLK)
void scan_p3_kernel() {
    int n = blockIdx.x * SBLK + threadIdx.x;
    int c = (n < NN) ? g_cur[n] : 0;
    int ex = block_excl_scan_256(c, nullptr);
    int off = g_bsum[blockIdx.x] + ex;
    if (n < NN) {
        g_off[n] = off;
        g_cur[n] = off;
        if (n == NN - 1) g_off[NN] = off + c;
    }
}

// ---------------------------------------------------------------------------
// Fill CSR: group source row ids by destination
// ---------------------------------------------------------------------------
__global__ void fill_kernel(const void* __restrict__ idx, int E) {
    int e = blockIdx.x * blockDim.x + threadIdx.x;
    if (e >= E) return;
    int r, c;
    if (g_is64) {
        const long long* p = (const long long*)idx;
        r = (int)__ldg(p + e);
        c = (int)__ldg(p + E + e);
    } else {
        const int* p = (const int*)idx;
        r = __ldg(p + e);
        c = __ldg(p + E + e);
    }
    int pos = atomicAdd(g_cur + c, 1);
    g_csr[pos] = (unsigned short)r;
}

// ---------------------------------------------------------------------------
// Fused gather-aggregate + tf32 tensor-core GEMM.  BM = 64 rows per block,
// static shared memory only (44 KB).
//   A[n] = deg>0 ? (sum_{r in nbr(n)} x[r]) / deg : x[n]
//   out[n][j] = sum_k A[n][k] * W[j][k] + b[j]
// ---------------------------------------------------------------------------
#define BM  64
#define SPA 132   // As row pitch (u32): 128 + 4 pad
#define SPW 20    // Ws row pitch (u32): 16 + 4 pad

__device__ __forceinline__ uint32_t f2tf32(float v) {
    uint32_t u;
    asm("cvt.rna.tf32.f32 %0, %1;" : "=r"(u) : "f"(v));
    return u;
}

__global__ __launch_bounds__(256)
void fused_kernel(const float4* __restrict__ x4,
                  const float* __restrict__ W,
                  const float* __restrict__ bias,
                  float* __restrict__ out, int N) {
    __shared__ uint32_t As[BM * SPA];    // 33792 B
    __shared__ uint32_t Ws[128 * SPW];   // 10240 B

    int tid  = threadIdx.x;
    int row0 = blockIdx.x * BM;
    int wid  = tid >> 5;
    int lane = tid & 31;

    // ---------------- Phase 1: gather-aggregate into As ----------------
    for (int rr = wid; rr < BM; rr += 8) {
        int n = row0 + rr;
        float4 acc = make_float4(0.f, 0.f, 0.f, 0.f);
        float scale = 1.0f;
        if (n < N) {
            int beg = g_off[n], end = g_off[n + 1];
            int deg = end - beg;
            if (deg == 0) {
                acc = __ldg(x4 + (size_t)n * 32 + lane);
            } else {
                for (int b = beg; b < end; b += 32) {
                    int rid = 0;
                    if (b + lane < end) rid = g_csr[b + lane];
                    int m = end - b; if (m > 32) m = 32;
                    #pragma unroll 4
                    for (int j = 0; j < m; j++) {
                        int r = __shfl_sync(0xffffffffu, rid, j);
                        float4 v = __ldg(x4 + (size_t)r * 32 + lane);
                        acc.x += v.x; acc.y += v.y; acc.z += v.z; acc.w += v.w;
                    }
                }
                scale = 1.0f / (float)deg;
            }
        }
        uint4 o;
        o.x = f2tf32(acc.x * scale);
        o.y = f2tf32(acc.y * scale);
        o.z = f2tf32(acc.z * scale);
        o.w = f2tf32(acc.w * scale);
        *(uint4*)(As + (size_t)rr * SPA + lane * 4) = o;
    }
    __syncthreads();

    // ---------------- Phase 2: tensor-core MMA ----------------
    int g  = lane >> 2;     // 0..7
    int c4 = lane & 3;      // 0..3
    int wy = wid >> 2;      // 0..1 -> 32 rows each
    int wx = wid & 3;       // 0..3 -> 32 cols each

    float acc[2][4][4];
    #pragma unroll
    for (int i = 0; i < 2; i++)
        #pragma unroll
        for (int j = 0; j < 4; j++)
            #pragma unroll
            for (int q = 0; q < 4; q++) acc[i][j][q] = 0.f;

    for (int k0 = 0; k0 < 128; k0 += 16) {
        // load W slab: Ws[n][kk] = tf32(W[n][k0+kk]); 512 float4 / 256 thr
        #pragma unroll
        for (int q = 0; q < 2; q++) {
            int lin  = tid + q * 256;      // 0..511
            int nrow = lin >> 2;           // 0..127
            int f4   = lin & 3;            // 0..3 -> 16 floats
            float4 wv = *(const float4*)(W + (size_t)nrow * 128 + k0 + f4 * 4);
            uint4 o;
            o.x = f2tf32(wv.x); o.y = f2tf32(wv.y);
            o.z = f2tf32(wv.z); o.w = f2tf32(wv.w);
            *(uint4*)(Ws + (size_t)nrow * SPW + f4 * 4) = o;
        }
        __syncthreads();

        #pragma unroll
        for (int ks = 0; ks < 16; ks += 8) {
            uint32_t bf[4][2];
            #pragma unroll
            for (int j = 0; j < 4; j++) {
                int n0 = wx * 32 + j * 8;
                bf[j][0] = Ws[(size_t)(n0 + g) * SPW + ks + c4];
                bf[j][1] = Ws[(size_t)(n0 + g) * SPW + ks + c4 + 4];
            }
            #pragma unroll
            for (int i = 0; i < 2; i++) {
                int m0 = wy * 32 + i * 16;
                int kk = k0 + ks;
                uint32_t a0 = As[(size_t)(m0 + g) * SPA + kk + c4];
                uint32_t a1 = As[(size_t)(m0 + g + 8) * SPA + kk + c4];
                uint32_t a2 = As[(size_t)(m0 + g) * SPA + kk + c4 + 4];
                uint32_t a3 = As[(size_t)(m0 + g + 8) * SPA + kk + c4 + 4];
                #pragma unroll
                for (int j = 0; j < 4; j++) {
                    asm volatile(
                        "mma.sync.aligned.m16n8k8.row.col.f32.tf32.tf32.f32 "
                        "{%0,%1,%2,%3}, {%4,%5,%6,%7}, {%8,%9}, {%0,%1,%2,%3};"
                        : "+f"(acc[i][j][0]), "+f"(acc[i][j][1]),
                          "+f"(acc[i][j][2]), "+f"(acc[i][j][3])
                        : "r"(a0), "r"(a1), "r"(a2), "r"(a3),
                          "r"(bf[j][0]), "r"(bf[j][1]));
                }
            }
        }
        __syncthreads();
    }

    // ---------------- epilogue: bias + store ----------------
    #pragma unroll
    for (int j = 0; j < 4; j++) {
        int n = wx * 32 + j * 8 + 2 * c4;
        float2 bb = *(const float2*)(bias + n);
        #pragma unroll
        for (int i = 0; i < 2; i++) {
            int mr = row0 + wy * 32 + i * 16 + g;
            if (mr < N) {
                float2 o;
                o.x = acc[i][j][0] + bb.x;
                o.y = acc[i][j][1] + bb.y;
                *(float2*)(out + (size_t)mr * 128 + n) = o;
            }
            int mr2 = mr + 8;
            if (mr2 < N) {
                float2 o;
                o.x = acc[i][j][2] + bb.x;
                o.y = acc[i][j][3] + bb.y;
                *(float2*)(out + (size_t)mr2 * 128 + n) = o;
            }
        }
    }
}

// ---------------------------------------------------------------------------
extern "C" void kernel_launch(void* const* d_in, const int* in_sizes, int n_in,
                              void* d_out, int out_size) {
    const float* x    = (const float*)d_in[0];
    const void*  idx  = d_in[1];
    const float* W    = (const float*)d_in[2];
    const float* bias = (const float*)d_in[3];
    float* out = (float*)d_out;

    int E = in_sizes[1] / 2;      // 1,600,000 regardless of int32/int64
    int N = in_sizes[0] / D;      // 50,000

    detect_kernel<<<1, 32>>>(idx);
    zero_cnt_kernel<<<(NN + 255) / 256, 256>>>();
    count_kernel<<<(E + 255) / 256, 256>>>(idx, E);
    scan_p1_kernel<<<NBLK, SBLK>>>();
    scan_p2_kernel<<<1, SBLK>>>();
    scan_p3_kernel<<<NBLK, SBLK>>>();
    fill_kernel<<<(E + 255) / 256, 256>>>(idx, E);
    fused_kernel<<<(N + BM - 1) / BM, 256>>>((const float4*)x, W, bias, out, N);
}